// round 11
// baseline (speedup 1.0000x reference)
#include <cuda_runtime.h>
#include <cstdint>
#include <cstddef>

#define N_PTS 8192
#define DIMS  128
#define KDIM  160            // 128 data + 8 ext (bias fold) + 24 zero; 5 k-steps of 32
#define KNBR  14
#define CAP   448
#define QS    24.0f          // int8 scale
#define C2    576.0f         // QS^2
#define RSTRB 176            // smem row stride bytes (16B-aligned, ldsm conflict-free: 11r mod 8 distinct)
#define TILEB (128 * RSTRB)  // 22528 B per 128-row tile

// ---------------- scratch ----------------
__device__ __align__(16) signed char g_XA[N_PTS * KDIM];  // ext = [127 x8, 0...]
__device__ __align__(16) signed char g_XB[N_PTS * KDIM];  // ext = [p0..p7 (sum=round(-c^2*sq/2/127)), 0...]
__device__ float  g_SQ[N_PTS];
__device__ int    g_THR[N_PTS * 2];                       // per (row, half) conservative threshold
__device__ int    g_CNT[N_PTS];
__device__ int2   g_CAND[(size_t)N_PTS * CAP];            // (int key, col)
__device__ int    g_NBR[N_PTS * KNBR];
__device__ double g_partial_bulk[1024];
__device__ double g_partial_corr[1024];

// ---------------- fast-math ----------------
__device__ __forceinline__ float f_sqrt(float x){ float r; asm("sqrt.approx.f32 %0, %1;" : "=f"(r) : "f"(x)); return r; }
__device__ __forceinline__ float f_rcp (float x){ float r; asm("rcp.approx.f32 %0, %1;"  : "=f"(r) : "f"(x)); return r; }
__device__ __forceinline__ float f_lg2 (float x){ float r; asm("lg2.approx.f32 %0, %1;"  : "=f"(r) : "f"(x)); return r; }
__device__ __forceinline__ float f_ex2 (float x){ float r; asm("ex2.approx.f32 %0, %1;"  : "=f"(r) : "f"(x)); return r; }

#define LN2F   0.69314718055994531f
#define LOG2EF 1.4426950408889634f

__device__ __forceinline__ void cp_async16(uint32_t dst, const void* src) {
    asm volatile("cp.async.cg.shared.global [%0], [%1], 16;" :: "r"(dst), "l"(src));
}
// int8 IMMA m16n8k32, s32 accumulate (exact)
__device__ __forceinline__ void mma_s8(int& c0, int& c1, int& c2, int& c3,
                                       uint32_t a0, uint32_t a1, uint32_t a2, uint32_t a3,
                                       uint32_t b0, uint32_t b1) {
    asm volatile("mma.sync.aligned.m16n8k32.row.col.s32.s8.s8.s32 "
                 "{%0,%1,%2,%3}, {%4,%5,%6,%7}, {%8,%9}, {%0,%1,%2,%3};"
                 : "+r"(c0), "+r"(c1), "+r"(c2), "+r"(c3)
                 : "r"(a0), "r"(a1), "r"(a2), "r"(a3), "r"(b0), "r"(b1));
}
__device__ __forceinline__ void ldsm4(uint32_t& r0, uint32_t& r1, uint32_t& r2, uint32_t& r3, uint32_t addr) {
    asm volatile("ldmatrix.sync.aligned.m8n8.x4.shared.b16 {%0,%1,%2,%3}, [%4];"
                 : "=r"(r0), "=r"(r1), "=r"(r2), "=r"(r3) : "r"(addr));
}

// ---------------- 1) prep: int8 quantize + bias fold + norms ----------------
__global__ void prep_kernel(const float* __restrict__ X) {
    int warp = threadIdx.x >> 5, lane = threadIdx.x & 31;
    int row  = blockIdx.x * 8 + warp;
    const float* xr = X + (size_t)row * DIMS;
    float v[4]; float s = 0.f;
    #pragma unroll
    for (int q = 0; q < 4; q++) { v[q] = xr[lane + q * 32]; s += v[q] * v[q]; }
    #pragma unroll
    for (int off = 16; off; off >>= 1) s += __shfl_xor_sync(0xffffffffu, s, off);
    s = __shfl_sync(0xffffffffu, s, 0);

    signed char* xa = g_XA + (size_t)row * KDIM;
    signed char* xb = g_XB + (size_t)row * KDIM;
    #pragma unroll
    for (int q = 0; q < 4; q++) {
        int qi = __float2int_rn(fminf(fmaxf(v[q] * QS, -127.f), 127.f));
        xa[lane + q * 32] = (signed char)qi;
        xb[lane + q * 32] = (signed char)qi;
    }
    // ext dims: A = 127 x8; B = 8-way split of M = round(-0.5*C2*s/127), sum exact
    int M  = __float2int_rn(-0.5f * C2 * s / 127.f);
    int q8 = M / 8, r8 = M - 8 * q8;           // |r8| <= 7
    int ar = (r8 < 0) ? -r8 : r8, sg = (r8 < 0) ? -1 : 1;
    if (lane < 8) {
        xa[128 + lane] = (signed char)127;
        int p = q8 + ((lane < ar) ? sg : 0);   // |p| <= 57+1
        xb[128 + lane] = (signed char)p;
    } else {
        xa[128 + 8 + (lane - 8)] = 0;
        xb[128 + 8 + (lane - 8)] = 0;
    }
    if (lane == 0) { g_SQ[row] = s; g_CNT[row] = 0; }
}

// ---- fragment addressing (warp tile 32x64 of a 128x128 tile; 4x2 warp grid) ----
struct FragAddr { uint32_t a_off[2]; uint32_t b_off[4]; };
__device__ __forceinline__ FragAddr frag_addr(int warp, int lane) {
    FragAddr f;
    int wm = warp & 3, wn = warp >> 2;
    #pragma unroll
    for (int mt = 0; mt < 2; mt++)
        f.a_off[mt] = (uint32_t)((wm * 32 + mt * 16 + (lane & 15)) * RSTRB + ((lane >> 4) ? 16 : 0));
    #pragma unroll
    for (int bq = 0; bq < 4; bq++)
        f.b_off[bq] = (uint32_t)((wn * 64 + bq * 16 + ((lane >> 3) & 2) * 4 + (lane & 7)) * RSTRB
                                 + ((lane >> 3) & 1) * 16);
    return f;
}
// 5 k-step int8 MMA over a 128x128 tile
__device__ __forceinline__ void tile_mma_s8(uint32_t sA_u, uint32_t sB_u, const FragAddr& f,
                                            int acc[2][8][4]) {
    #pragma unroll
    for (int mt = 0; mt < 2; mt++)
        #pragma unroll
        for (int nt = 0; nt < 8; nt++)
            #pragma unroll
            for (int q = 0; q < 4; q++) acc[mt][nt][q] = 0;
    #pragma unroll
    for (int kk = 0; kk < 5; kk++) {
        uint32_t kof = (uint32_t)(kk * 32);
        uint32_t afr[2][4];
        #pragma unroll
        for (int mt = 0; mt < 2; mt++)
            ldsm4(afr[mt][0], afr[mt][1], afr[mt][2], afr[mt][3], sA_u + f.a_off[mt] + kof);
        uint32_t bfr[8][2];
        #pragma unroll
        for (int bq = 0; bq < 4; bq++)
            ldsm4(bfr[2*bq][0], bfr[2*bq][1], bfr[2*bq+1][0], bfr[2*bq+1][1], sB_u + f.b_off[bq] + kof);
        #pragma unroll
        for (int mt = 0; mt < 2; mt++)
            #pragma unroll
            for (int nt = 0; nt < 8; nt++)
                mma_s8(acc[mt][nt][0], acc[mt][nt][1], acc[mt][nt][2], acc[mt][nt][3],
                       afr[mt][0], afr[mt][1], afr[mt][2], afr[mt][3],
                       bfr[nt][0], bfr[nt][1]);
    }
}

// ======================= Phase 1: per-(row, half) threshold =======================
// 128 blocks: rb = b>>1 (128-row block), half = b&1 (512 subsample cols = 4 tiles)
#define P1_SB  TILEB
#define P1_SC  (2 * TILEB)                 // score tile s32 128x132
#define P1_ST  (2 * TILEB + 128 * 132 * 4) // stage 256*14 ints
#define P1_TOT (P1_ST + 14336)

__global__ __launch_bounds__(256, 1) void thresh_kernel() {
    extern __shared__ __align__(16) char smem[];
    uint32_t sA_u = (uint32_t)__cvta_generic_to_shared(smem);
    uint32_t sB_u = sA_u + P1_SB;
    int* sSc = (int*)(smem + P1_SC);
    int* stK = (int*)(smem + P1_ST);

    int tid = threadIdx.x;
    int rb = blockIdx.x >> 1, half = blockIdx.x & 1;
    int rowBlk = rb * 128;
    int warp = tid >> 5, lane = tid & 31;
    int wm = warp & 3, wn = warp >> 2;
    int grp = lane >> 2, tig = lane & 3;
    FragAddr fa = frag_addr(warp, lane);

    // A tile: 1280 chunks of 16B
    #pragma unroll
    for (int i = 0; i < 5; i++) {
        int c = tid + i * 256;
        int r = c / 10, q = c % 10;
        cp_async16(sA_u + (uint32_t)(r * RSTRB + q * 16),
                   g_XA + (size_t)(rowBlk + r) * KDIM + q * 16);
    }
    asm volatile("cp.async.commit_group;");

    int bk[KNBR];
    #pragma unroll
    for (int s = 0; s < KNBR; s++) bk[s] = (int)0x80000000;
    int srow = tid >> 1, seg = tid & 1;

    for (int t = 0; t < 4; t++) {
        #pragma unroll
        for (int i = 0; i < 5; i++) {
            int c = tid + i * 256;
            int r = c / 10, q = c % 10;
            int j = 8 * (half * 512 + t * 128 + r);
            cp_async16(sB_u + (uint32_t)(r * RSTRB + q * 16),
                       g_XB + (size_t)j * KDIM + q * 16);
        }
        asm volatile("cp.async.commit_group;");
        asm volatile("cp.async.wait_group 0;");
        __syncthreads();

        int acc[2][8][4];
        tile_mma_s8(sA_u, sB_u, fa, acc);

        #pragma unroll
        for (int mt = 0; mt < 2; mt++)
            #pragma unroll
            for (int nt = 0; nt < 8; nt++) {
                int lr = wm * 32 + mt * 16 + grp;
                int lc = wn * 64 + nt * 8 + tig * 2;
                sSc[lr * 132 + lc]           = acc[mt][nt][0];
                sSc[lr * 132 + lc + 1]       = acc[mt][nt][1];
                sSc[(lr + 8) * 132 + lc]     = acc[mt][nt][2];
                sSc[(lr + 8) * 132 + lc + 1] = acc[mt][nt][3];
            }
        __syncthreads();
        const int* prow = sSc + srow * 132 + seg * 64;
        #pragma unroll 8
        for (int c = 0; c < 64; c++) {
            int v = prow[c];
            if (v > bk[KNBR - 1]) {
                int cv = v;
                #pragma unroll
                for (int s = 0; s < KNBR; s++)
                    if (cv > bk[s]) { int tf = bk[s]; bk[s] = cv; cv = tf; }
            }
        }
        __syncthreads();
    }
    #pragma unroll
    for (int s = 0; s < KNBR; s++) stK[tid * KNBR + s] = bk[s];
    __syncthreads();
    if (tid < 128) {
        const int* k0 = stK + (tid * 2) * KNBR;
        const int* k1 = stK + (tid * 2 + 1) * KNBR;
        int p0 = 0, p1 = 0, v = 0;
        #pragma unroll
        for (int s = 0; s < KNBR; s++) {
            if (k0[p0] >= k1[p1]) v = k0[p0++]; else v = k1[p1++];
        }
        g_THR[(rowBlk + tid) * 2 + half] = v;   // 14th of this half's 512-subsample
    }
}

// ======================= Phase 2: full int8 GEMM + register filter =======================
#define P2_TOT (3 * TILEB)   // A + 2 B buffers = 67584 -> 2 blocks/SM

__global__ __launch_bounds__(256, 2) void filter_kernel() {
    extern __shared__ __align__(16) char smem[];
    uint32_t sA_u = (uint32_t)__cvta_generic_to_shared(smem);
    uint32_t sB_u = sA_u + TILEB;

    int tid = threadIdx.x;
    int warp = tid >> 5, lane = tid & 31;
    int wm = warp & 3, wn = warp >> 2;
    int grp = lane >> 2, tig = lane & 3;
    int rb = blockIdx.x >> 2, quarter = blockIdx.x & 3;
    int rowBlk = rb * 128, colBase = quarter * 2048;
    FragAddr fa = frag_addr(warp, lane);

    #pragma unroll
    for (int i = 0; i < 5; i++) {
        int c = tid + i * 256;
        int r = c / 10, q = c % 10;
        cp_async16(sA_u + (uint32_t)(r * RSTRB + q * 16),
                   g_XA + (size_t)(rowBlk + r) * KDIM + q * 16);
        cp_async16(sB_u + (uint32_t)(r * RSTRB + q * 16),
                   g_XB + (size_t)(colBase + r) * KDIM + q * 16);
    }
    asm volatile("cp.async.commit_group;");
    #pragma unroll
    for (int i = 0; i < 5; i++) {
        int c = tid + i * 256;
        int r = c / 10, q = c % 10;
        cp_async16(sB_u + (uint32_t)TILEB + (uint32_t)(r * RSTRB + q * 16),
                   g_XB + (size_t)(colBase + 128 + r) * KDIM + q * 16);
    }
    asm volatile("cp.async.commit_group;");

    int T[2][2];
    #pragma unroll
    for (int mt = 0; mt < 2; mt++)
        #pragma unroll
        for (int rh = 0; rh < 2; rh++) {
            int row = rowBlk + wm * 32 + mt * 16 + grp + rh * 8;
            int t0 = g_THR[row * 2], t1 = g_THR[row * 2 + 1];
            T[mt][rh] = (t0 > t1) ? t0 : t1;   // tighter of two conservative bounds
        }

    asm volatile("cp.async.wait_group 1;");

    for (int t = 0; t < 16; t++) {
        __syncthreads();
        uint32_t bbuf = sB_u + (uint32_t)(t & 1) * (uint32_t)TILEB;

        int acc[2][8][4];
        tile_mma_s8(sA_u, bbuf, fa, acc);

        int colT = colBase + t * 128 + wn * 64 + tig * 2;
        #pragma unroll
        for (int mt = 0; mt < 2; mt++) {
            #pragma unroll
            for (int rh = 0; rh < 2; rh++) {
                int gm = acc[mt][0][rh * 2];
                if (acc[mt][0][rh * 2 + 1] > gm) gm = acc[mt][0][rh * 2 + 1];
                #pragma unroll
                for (int nt = 1; nt < 8; nt++) {
                    if (acc[mt][nt][rh * 2]     > gm) gm = acc[mt][nt][rh * 2];
                    if (acc[mt][nt][rh * 2 + 1] > gm) gm = acc[mt][nt][rh * 2 + 1];
                }
                int Tf = T[mt][rh];
                if (gm >= Tf) {
                    int row = rowBlk + wm * 32 + mt * 16 + grp + rh * 8;
                    #pragma unroll
                    for (int nt = 0; nt < 8; nt++) {
                        int v0 = acc[mt][nt][rh * 2], v1 = acc[mt][nt][rh * 2 + 1];
                        if (v0 >= Tf) {
                            int pos = atomicAdd(&g_CNT[row], 1);
                            if (pos < CAP) g_CAND[(size_t)row * CAP + pos] = make_int2(v0, colT + nt * 8);
                        }
                        if (v1 >= Tf) {
                            int pos = atomicAdd(&g_CNT[row], 1);
                            if (pos < CAP) g_CAND[(size_t)row * CAP + pos] = make_int2(v1, colT + nt * 8 + 1);
                        }
                    }
                }
            }
        }
        __syncthreads();
        if (t + 2 < 16) {
            uint32_t bdst = sB_u + (uint32_t)(t & 1) * (uint32_t)TILEB;
            const signed char* bsrc = g_XB + (size_t)(colBase + (t + 2) * 128) * KDIM;
            #pragma unroll
            for (int i = 0; i < 5; i++) {
                int c = tid + i * 256;
                int r = c / 10, q = c % 10;
                cp_async16(bdst + (uint32_t)(r * RSTRB + q * 16), bsrc + (size_t)r * KDIM + q * 16);
            }
            asm volatile("cp.async.commit_group;");
            asm volatile("cp.async.wait_group 1;");
        } else if (t + 1 < 16) {
            asm volatile("cp.async.wait_group 0;");
        }
    }
}

// ======================= Phase 3: thread-per-row top-14 select =======================
__global__ void select_topk() {
    int row = blockIdx.x * 256 + threadIdx.x;
    int cnt = g_CNT[row]; if (cnt > CAP) cnt = CAP;
    const int2* cand = g_CAND + (size_t)row * CAP;

    int bk[KNBR], bi[KNBR];
    #pragma unroll
    for (int s = 0; s < KNBR; s++) { bk[s] = (int)0x80000000; bi[s] = 0x7fffffff; }
    for (int c = 0; c < cnt; c++) {
        int2 e = cand[c];
        if (e.x > bk[KNBR - 1] || (e.x == bk[KNBR - 1] && e.y < bi[KNBR - 1])) {
            int cv = e.x, ci = e.y;
            #pragma unroll
            for (int s = 0; s < KNBR; s++)
                if (cv > bk[s] || (cv == bk[s] && ci < bi[s])) {
                    int tf = bk[s]; bk[s] = cv; cv = tf;
                    int ti = bi[s]; bi[s] = ci; ci = ti;
                }
        }
    }
    #pragma unroll
    for (int s = 0; s < KNBR; s++) g_NBR[row * KNBR + s] = bi[s];
}

// ---------------- bulk lo-dim loss: exact triangular grid (528 blocks) ----------------
__global__ void bulk_kernel(const float* __restrict__ LO) {
    int b = blockIdx.x;
    int i = (int)(32.5f - f_sqrt(32.5f * 32.5f - 2.0f * (float)b));
    while ((i + 1) * 32 - ((i + 1) * i) / 2 <= b) i++;
    while (i * 32 - (i * (i - 1)) / 2 > b) i--;
    int j = i + (b - (i * 32 - (i * (i - 1)) / 2));
    int ibase = i * 256, jbase = j * 256;

    __shared__ float2 sLo[256];
    __shared__ double sred[256];
    int tid = threadIdx.x;
    const float2* lo2 = (const float2*)LO;
    int gi = ibase + tid;
    float2 me = lo2[gi];
    sLo[tid] = lo2[jbase + tid];
    __syncthreads();

    float accf = 0.f;
    if (j > i) {
        #pragma unroll 4
        for (int c = 0; c < 256; c++) {
            float2 o = sLo[c];
            float dx = me.x - o.x, dy = me.y - o.y;
            float d = f_sqrt(fmaf(dx, dx, dy * dy));
            float r = f_rcp(1.0f + d);
            accf += f_lg2((1.0f - r) + 1e-10f);
        }
        accf *= 2.0f;
    } else {
        #pragma unroll 4
        for (int c = 0; c < 256; c++) {
            int jg = jbase + c;
            float2 o = sLo[c];
            float dx = me.x - o.x, dy = me.y - o.y;
            float d = f_sqrt(fmaf(dx, dx, dy * dy));
            float r = f_rcp(1.0f + d);
            float term = f_lg2((1.0f - r) + 1e-10f);
            float w = (jg > gi) ? 2.0f : ((jg == gi) ? 1.0f : 0.0f);
            accf += w * term;
        }
    }
    sred[tid] = (double)(accf * LN2F);
    __syncthreads();
    for (int off = 128; off; off >>= 1) { if (tid < off) sred[tid] += sred[tid + off]; __syncthreads(); }
    if (tid == 0) g_partial_bulk[b] = sred[0];
}

// ---------------- exact neighbor correction ----------------
__global__ void corr_kernel(const float* __restrict__ X, const float* __restrict__ LO) {
    __shared__ double wsum[8];
    int warp = threadIdx.x >> 5, lane = threadIdx.x & 31;
    int row  = blockIdx.x * 8 + warp;
    const float* xi = X + (size_t)row * DIMS;
    float a0 = xi[lane], a1 = xi[lane + 32], a2 = xi[lane + 64], a3 = xi[lane + 96];
    const float2* lo2 = (const float2*)LO;
    float2 li = lo2[row];
    float sqi = g_SQ[row];

    float acc = 0.f;
    for (int n = 0; n < KNBR; n++) {
        int j = g_NBR[row * KNBR + n];
        const float* xj = X + (size_t)j * DIMS;
        float dot = a0 * xj[lane] + a1 * xj[lane + 32] + a2 * xj[lane + 64] + a3 * xj[lane + 96];
        #pragma unroll
        for (int off = 16; off; off >>= 1) dot += __shfl_xor_sync(0xffffffffu, dot, off);
        float d2h = fmaxf(sqi + g_SQ[j] - 2.f * dot, 0.f);
        float hd = f_sqrt(d2h);
        float hs = f_ex2(-LOG2EF * hd);
        float2 lj = lo2[j];
        float dx = li.x - lj.x, dy = li.y - lj.y;
        float ld = f_sqrt(fmaf(dx, dx, dy * dy));
        float r  = f_rcp(1.0f + ld);
        float A  = hs * (f_lg2(r + 1e-10f) * LN2F);
        float Bs = f_lg2((1.0f - r) + 1e-10f) * LN2F;
        acc += (A - Bs);
    }
    if (lane == 0) wsum[warp] = (double)acc;
    __syncthreads();
    if (threadIdx.x == 0) {
        double s = 0;
        for (int k = 0; k < 8; k++) s += wsum[k];
        g_partial_corr[blockIdx.x] = s;
    }
}

// ---------------- deterministic final reduce ----------------
__global__ void final_kernel(float* __restrict__ out) {
    __shared__ double sred[256];
    int t = threadIdx.x;
    double s = 0;
    for (int k = t; k < 528;  k += 256) s += g_partial_bulk[k];
    for (int k = t; k < 1024; k += 256) s += g_partial_corr[k];
    sred[t] = s;
    __syncthreads();
    for (int off = 128; off; off >>= 1) { if (t < off) sred[t] += sred[t + off]; __syncthreads(); }
    if (t == 0) out[0] = (float)(-(sred[0] / 67108864.0) * 100.0);
}

// ---------------- launch ----------------
extern "C" void kernel_launch(void* const* d_in, const int* in_sizes, int n_in,
                              void* d_out, int out_size) {
    const float* X; const float* LO;
    if (in_sizes[0] == N_PTS * DIMS) { X = (const float*)d_in[0]; LO = (const float*)d_in[1]; }
    else                             { X = (const float*)d_in[1]; LO = (const float*)d_in[0]; }

    cudaFuncSetAttribute(thresh_kernel, cudaFuncAttributeMaxDynamicSharedMemorySize, P1_TOT);
    cudaFuncSetAttribute(filter_kernel, cudaFuncAttributeMaxDynamicSharedMemorySize, P2_TOT);

    prep_kernel  <<<N_PTS / 8, 256>>>(X);
    thresh_kernel<<<128, 256, P1_TOT>>>();
    filter_kernel<<<256, 256, P2_TOT>>>();
    select_topk  <<<N_PTS / 256, 256>>>();
    bulk_kernel  <<<528, 256>>>(LO);
    corr_kernel  <<<N_PTS / 8, 256>>>(X, LO);
    final_kernel <<<1, 256>>>((float*)d_out);
}

// round 12
// speedup vs baseline: 1.8212x; 1.8212x over previous
#include <cuda_runtime.h>
#include <cstdint>
#include <cstddef>

#define N_PTS 8192
#define DIMS  128
#define KNBR  14
#define CAP   448
#define QS    24.0f
#define ROWB  136               // smem panel row stride (bytes): 34 words -> conflict-free
#define PANELB (128 * ROWB)     // 17408 B per 128-row int8 panel
#define NPAN  64
#define NPAIR 2080

// ---------------- scratch ----------------
__device__ __align__(16) signed char g_XQ[N_PTS * DIMS];   // 1 MB int8, L2-resident
__device__ int       g_SQQ[N_PTS];                          // |q_i|^2 exact int
__device__ float     g_SQ[N_PTS];                           // fp32 row norms (for corr)
__device__ int       g_THR[N_PTS * 2];
__device__ int       g_CNT[N_PTS];
__device__ long long g_CAND[(size_t)N_PTS * CAP];           // packed (key<<13 | 8191-col)
__device__ int       g_NBR[N_PTS * KNBR];
__device__ double    g_pb[1024];
__device__ double    g_pc[1024];

// ---------------- fast-math ----------------
__device__ __forceinline__ float f_sqrt(float x){ float r; asm("sqrt.approx.f32 %0, %1;" : "=f"(r) : "f"(x)); return r; }
__device__ __forceinline__ float f_rcp (float x){ float r; asm("rcp.approx.f32 %0, %1;"  : "=f"(r) : "f"(x)); return r; }
__device__ __forceinline__ float f_lg2 (float x){ float r; asm("lg2.approx.f32 %0, %1;"  : "=f"(r) : "f"(x)); return r; }
__device__ __forceinline__ float f_ex2 (float x){ float r; asm("ex2.approx.f32 %0, %1;"  : "=f"(r) : "f"(x)); return r; }

#define LN2F   0.69314718055994531f
#define LOG2EF 1.4426950408889634f

__device__ __forceinline__ void cp_async8(uint32_t dst, const void* src) {
    asm volatile("cp.async.ca.shared.global [%0], [%1], 8;" :: "r"(dst), "l"(src));
}

// ---------------- 1) prep: quantize + norms + counter reset ----------------
__global__ void prep_kernel(const float* __restrict__ X) {
    int warp = threadIdx.x >> 5, lane = threadIdx.x & 31;
    int row  = blockIdx.x * 8 + warp;
    const float* xr = X + (size_t)row * DIMS + lane * 4;
    float v0 = xr[0], v1 = xr[1], v2 = xr[2], v3 = xr[3];
    int q0 = __float2int_rn(fminf(fmaxf(v0 * QS, -127.f), 127.f));
    int q1 = __float2int_rn(fminf(fmaxf(v1 * QS, -127.f), 127.f));
    int q2 = __float2int_rn(fminf(fmaxf(v2 * QS, -127.f), 127.f));
    int q3 = __float2int_rn(fminf(fmaxf(v3 * QS, -127.f), 127.f));
    ((int*)g_XQ)[row * 32 + lane] =
        (q0 & 0xff) | ((q1 & 0xff) << 8) | ((q2 & 0xff) << 16) | (q3 << 24);
    float s  = v0*v0 + v1*v1 + v2*v2 + v3*v3;
    int  sq  = q0*q0 + q1*q1 + q2*q2 + q3*q3;
    #pragma unroll
    for (int off = 16; off; off >>= 1) {
        s  += __shfl_xor_sync(0xffffffffu, s,  off);
        sq += __shfl_xor_sync(0xffffffffu, sq, off);
    }
    if (lane == 0) { g_SQ[row] = s; g_SQQ[row] = sq; g_CNT[row] = 0; }
}

// ---------------- dp4a tile core: 128x128 outputs, thread (tx,ty) owns rows ty*8+j, cols tx+16i
__device__ __forceinline__ void tile_dp4a(const char* sA, const char* sB, int tx, int ty,
                                          int acc[8][8]) {
    #pragma unroll
    for (int j = 0; j < 8; j++)
        #pragma unroll
        for (int i = 0; i < 8; i++) acc[j][i] = 0;
    const char* aBase = sA + (ty * 8) * ROWB;
    const char* bBase = sB + tx * ROWB;
    #pragma unroll 4
    for (int p = 0; p < 16; p++) {
        int2 a[8], b[8];
        #pragma unroll
        for (int j = 0; j < 8; j++) a[j] = *(const int2*)(aBase + j * ROWB + p * 8);
        #pragma unroll
        for (int i = 0; i < 8; i++) b[i] = *(const int2*)(bBase + i * 16 * ROWB + p * 8);
        #pragma unroll
        for (int j = 0; j < 8; j++)
            #pragma unroll
            for (int i = 0; i < 8; i++) {
                acc[j][i] = __dp4a(a[j].x, b[i].x, acc[j][i]);
                acc[j][i] = __dp4a(a[j].y, b[i].y, acc[j][i]);
            }
    }
}

// ======================= Phase 1: per-(row, half) threshold =======================
// 128 blocks: rb = b>>1, half = b&1; 4 tiles of 128 subsampled cols (j = 8m)
#define T_SB   PANELB
#define T_SC   (2 * PANELB)
#define T_ST   (2 * PANELB + 128 * 132 * 4)
#define T_TOT  (T_ST + 256 * KNBR * 4)       // 116736

__global__ __launch_bounds__(256, 1) void thresh_kernel() {
    extern __shared__ __align__(16) char smem[];
    char* sA = smem;
    char* sB = smem + T_SB;
    int*  sSc = (int*)(smem + T_SC);
    int*  stK = (int*)(smem + T_ST);
    __shared__ int sSqqT[128];
    uint32_t sA_u = (uint32_t)__cvta_generic_to_shared(sA);
    uint32_t sB_u = (uint32_t)__cvta_generic_to_shared(sB);

    int tid = threadIdx.x;
    int rb = blockIdx.x >> 1, half = blockIdx.x & 1;
    int rowBlk = rb * 128;
    int tx = tid & 15, ty = tid >> 4;

    #pragma unroll
    for (int i = 0; i < 8; i++) {
        int c = tid + i * 256;
        int r = c >> 4, q = c & 15;
        cp_async8(sA_u + (uint32_t)(r * ROWB + q * 8), g_XQ + (size_t)(rowBlk + r) * DIMS + q * 8);
    }
    asm volatile("cp.async.commit_group;");

    int bk[KNBR];
    #pragma unroll
    for (int s = 0; s < KNBR; s++) bk[s] = (int)0x80000000;
    int srow = tid >> 1, seg = tid & 1;

    for (int t = 0; t < 4; t++) {
        #pragma unroll
        for (int i = 0; i < 8; i++) {
            int c = tid + i * 256;
            int r = c >> 4, q = c & 15;
            int j = 8 * (half * 512 + t * 128 + r);
            cp_async8(sB_u + (uint32_t)(r * ROWB + q * 8), g_XQ + (size_t)j * DIMS + q * 8);
        }
        if (tid < 128) sSqqT[tid] = g_SQQ[8 * (half * 512 + t * 128 + tid)];
        asm volatile("cp.async.commit_group;");
        asm volatile("cp.async.wait_group 0;");
        __syncthreads();

        int acc[8][8];
        tile_dp4a(sA, sB, tx, ty, acc);

        #pragma unroll
        for (int j = 0; j < 8; j++)
            #pragma unroll
            for (int i = 0; i < 8; i++) {
                int col = tx + 16 * i;
                sSc[(ty * 8 + j) * 132 + col] = 2 * acc[j][i] - sSqqT[col];
            }
        __syncthreads();

        const int* prow = sSc + srow * 132 + seg * 64;
        #pragma unroll 8
        for (int c = 0; c < 64; c++) {
            int v = prow[c];
            if (v > bk[KNBR - 1]) {
                int cv = v;
                #pragma unroll
                for (int s = 0; s < KNBR; s++)
                    if (cv > bk[s]) { int tf = bk[s]; bk[s] = cv; cv = tf; }
            }
        }
        __syncthreads();
    }
    #pragma unroll
    for (int s = 0; s < KNBR; s++) stK[tid * KNBR + s] = bk[s];
    __syncthreads();
    if (tid < 128) {
        const int* k0 = stK + (tid * 2) * KNBR;
        const int* k1 = stK + (tid * 2 + 1) * KNBR;
        int p0 = 0, p1 = 0, v = 0;
        #pragma unroll
        for (int s = 0; s < KNBR; s++) {
            if (k0[p0] >= k1[p1]) v = k0[p0++]; else v = k1[p1++];
        }
        g_THR[(rowBlk + tid) * 2 + half] = v;
    }
}

// ======================= Phase 2: symmetric dp4a GEMM + filter =======================
__global__ __launch_bounds__(256, 2) void filter_kernel() {
    __shared__ __align__(16) char sAbuf[PANELB];
    __shared__ __align__(16) char sBbuf[PANELB];
    __shared__ int sTI[128], sSqI[128], sTJ[128], sSqJ[128];
    uint32_t sA_u = (uint32_t)__cvta_generic_to_shared(sAbuf);
    uint32_t sB_u = (uint32_t)__cvta_generic_to_shared(sBbuf);

    int tid = threadIdx.x;
    int tx = tid & 15, ty = tid >> 4;

    // decode upper-tri (I <= J)
    int b = blockIdx.x;
    int I = (int)floorf(64.5f - f_sqrt(64.5f * 64.5f - 2.0f * (float)b));
    while (64 * (I + 1) - ((I + 1) * I) / 2 <= b) I++;
    while (64 * I - (I * (I - 1)) / 2 > b) I--;
    int J = I + (b - (64 * I - (I * (I - 1)) / 2));
    int Ibase = I * 128, Jbase = J * 128;

    #pragma unroll
    for (int i = 0; i < 8; i++) {
        int c = tid + i * 256;
        int r = c >> 4, q = c & 15;
        cp_async8(sA_u + (uint32_t)(r * ROWB + q * 8), g_XQ + (size_t)(Ibase + r) * DIMS + q * 8);
        cp_async8(sB_u + (uint32_t)(r * ROWB + q * 8), g_XQ + (size_t)(Jbase + r) * DIMS + q * 8);
    }
    asm volatile("cp.async.commit_group;");
    if (tid < 128) {
        int r = Ibase + tid;
        int t0 = g_THR[r * 2], t1 = g_THR[r * 2 + 1];
        sTI[tid] = (t0 > t1) ? t0 : t1;
        sSqI[tid] = g_SQQ[r];
    } else {
        int r = Jbase + (tid - 128);
        int t0 = g_THR[r * 2], t1 = g_THR[r * 2 + 1];
        sTJ[tid - 128] = (t0 > t1) ? t0 : t1;
        sSqJ[tid - 128] = g_SQQ[r];
    }
    asm volatile("cp.async.wait_group 0;");
    __syncthreads();

    int acc[8][8];
    tile_dp4a(sAbuf, sBbuf, tx, ty, acc);

    int TI[8], sqI[8], TJ[8], sqJ[8];
    #pragma unroll
    for (int j = 0; j < 8; j++) { TI[j] = sTI[ty * 8 + j]; sqI[j] = sSqI[ty * 8 + j]; }
    #pragma unroll
    for (int i = 0; i < 8; i++) { TJ[i] = sTJ[tx + 16 * i]; sqJ[i] = sSqJ[tx + 16 * i]; }

    int minSqJ = sqJ[0], minSqI = sqI[0];
    #pragma unroll
    for (int i = 1; i < 8; i++) if (sqJ[i] < minSqJ) minSqJ = sqJ[i];
    #pragma unroll
    for (int j = 1; j < 8; j++) if (sqI[j] < minSqI) minSqI = sqI[j];

    // direction I: key = 2v - sqq_col vs TI[row]
    #pragma unroll
    for (int j = 0; j < 8; j++) {
        int mv = acc[j][0];
        #pragma unroll
        for (int i = 1; i < 8; i++) if (acc[j][i] > mv) mv = acc[j][i];
        if (2 * mv - minSqJ >= TI[j]) {
            int row = Ibase + ty * 8 + j;
            #pragma unroll
            for (int i = 0; i < 8; i++) {
                int key = 2 * acc[j][i] - sqJ[i];
                if (key >= TI[j]) {
                    int col = Jbase + tx + 16 * i;
                    int pos = atomicAdd(&g_CNT[row], 1);
                    if (pos < CAP)
                        g_CAND[(size_t)row * CAP + pos] =
                            ((long long)key << 13) | (long long)(8191 - col);
                }
            }
        }
    }
    // direction J (off-diagonal only): key = 2v - sqq_row vs TJ[col]
    if (I != J) {
        #pragma unroll
        for (int i = 0; i < 8; i++) {
            int mv = acc[0][i];
            #pragma unroll
            for (int j = 1; j < 8; j++) if (acc[j][i] > mv) mv = acc[j][i];
            if (2 * mv - minSqI >= TJ[i]) {
                int row = Jbase + tx + 16 * i;
                #pragma unroll
                for (int j = 0; j < 8; j++) {
                    int key = 2 * acc[j][i] - sqI[j];
                    if (key >= TJ[i]) {
                        int col = Ibase + ty * 8 + j;
                        int pos = atomicAdd(&g_CNT[row], 1);
                        if (pos < CAP)
                            g_CAND[(size_t)row * CAP + pos] =
                                ((long long)key << 13) | (long long)(8191 - col);
                    }
                }
            }
        }
    }
}

// ======================= Phase 3: warp-per-row top-14 =======================
__global__ void select_topk() {
    int warp = threadIdx.x >> 5, lane = threadIdx.x & 31;
    int row  = blockIdx.x * 8 + warp;
    int cnt = g_CNT[row]; if (cnt > CAP) cnt = CAP;
    const long long* cand = g_CAND + (size_t)row * CAP;
    const long long MINV = 0x8000000000000000LL;

    long long bk[KNBR];
    #pragma unroll
    for (int s = 0; s < KNBR; s++) bk[s] = MINV;
    for (int c = lane; c < cnt; c += 32) {
        long long v = cand[c];
        if (v > bk[KNBR - 1]) {
            long long cv = v;
            #pragma unroll
            for (int s = 0; s < KNBR; s++)
                if (cv > bk[s]) { long long tf = bk[s]; bk[s] = cv; cv = tf; }
        }
    }
    for (int r = 0; r < KNBR; r++) {
        long long m = bk[0];
        int owner = lane;
        #pragma unroll
        for (int off = 16; off; off >>= 1) {
            long long ov = __shfl_xor_sync(0xffffffffu, m, off);
            int       ow = __shfl_xor_sync(0xffffffffu, owner, off);
            if (ov > m) { m = ov; owner = ow; }
        }
        if (lane == owner) {
            #pragma unroll
            for (int s = 0; s < KNBR - 1; s++) bk[s] = bk[s + 1];
            bk[KNBR - 1] = MINV;
        }
        if (lane == 0) g_NBR[row * KNBR + r] = 8191 - (int)(m & 8191);
    }
}

// ---------------- bulk lo-dim loss: exact triangular grid ----------------
__global__ void bulk_kernel(const float* __restrict__ LO) {
    int b = blockIdx.x;
    int i = (int)(32.5f - f_sqrt(32.5f * 32.5f - 2.0f * (float)b));
    while ((i + 1) * 32 - ((i + 1) * i) / 2 <= b) i++;
    while (i * 32 - (i * (i - 1)) / 2 > b) i--;
    int j = i + (b - (i * 32 - (i * (i - 1)) / 2));
    int ibase = i * 256, jbase = j * 256;

    __shared__ float2 sLo[256];
    __shared__ double sred[256];
    int tid = threadIdx.x;
    const float2* lo2 = (const float2*)LO;
    int gi = ibase + tid;
    float2 me = lo2[gi];
    sLo[tid] = lo2[jbase + tid];
    __syncthreads();

    float accf = 0.f;
    if (j > i) {
        #pragma unroll 4
        for (int c = 0; c < 256; c++) {
            float2 o = sLo[c];
            float dx = me.x - o.x, dy = me.y - o.y;
            float d = f_sqrt(fmaf(dx, dx, dy * dy));
            float r = f_rcp(1.0f + d);
            accf += f_lg2((1.0f - r) + 1e-10f);
        }
        accf *= 2.0f;
    } else {
        #pragma unroll 4
        for (int c = 0; c < 256; c++) {
            int jg = jbase + c;
            float2 o = sLo[c];
            float dx = me.x - o.x, dy = me.y - o.y;
            float d = f_sqrt(fmaf(dx, dx, dy * dy));
            float r = f_rcp(1.0f + d);
            float term = f_lg2((1.0f - r) + 1e-10f);
            float w = (jg > gi) ? 2.0f : ((jg == gi) ? 1.0f : 0.0f);
            accf += w * term;
        }
    }
    sred[tid] = (double)(accf * LN2F);
    __syncthreads();
    for (int off = 128; off; off >>= 1) { if (tid < off) sred[tid] += sred[tid + off]; __syncthreads(); }
    if (tid == 0) g_pb[b] = sred[0];
}

// ---------------- exact neighbor correction ----------------
__global__ void corr_kernel(const float* __restrict__ X, const float* __restrict__ LO) {
    __shared__ double wsum[8];
    int warp = threadIdx.x >> 5, lane = threadIdx.x & 31;
    int row  = blockIdx.x * 8 + warp;
    const float* xi = X + (size_t)row * DIMS;
    float a0 = xi[lane], a1 = xi[lane + 32], a2 = xi[lane + 64], a3 = xi[lane + 96];
    const float2* lo2 = (const float2*)LO;
    float2 li = lo2[row];
    float sqi = g_SQ[row];

    float acc = 0.f;
    for (int n = 0; n < KNBR; n++) {
        int j = g_NBR[row * KNBR + n];
        const float* xj = X + (size_t)j * DIMS;
        float dot = a0 * xj[lane] + a1 * xj[lane + 32] + a2 * xj[lane + 64] + a3 * xj[lane + 96];
        #pragma unroll
        for (int off = 16; off; off >>= 1) dot += __shfl_xor_sync(0xffffffffu, dot, off);
        float d2h = fmaxf(sqi + g_SQ[j] - 2.f * dot, 0.f);
        float hd = f_sqrt(d2h);
        float hs = f_ex2(-LOG2EF * hd);
        float2 lj = lo2[j];
        float dx = li.x - lj.x, dy = li.y - lj.y;
        float ld = f_sqrt(fmaf(dx, dx, dy * dy));
        float r  = f_rcp(1.0f + ld);
        float A  = hs * (f_lg2(r + 1e-10f) * LN2F);
        float Bs = f_lg2((1.0f - r) + 1e-10f) * LN2F;
        acc += (A - Bs);
    }
    if (lane == 0) wsum[warp] = (double)acc;
    __syncthreads();
    if (threadIdx.x == 0) {
        double s = 0;
        for (int k = 0; k < 8; k++) s += wsum[k];
        g_pc[blockIdx.x] = s;
    }
}

// ---------------- deterministic final reduce ----------------
__global__ void final_kernel(float* __restrict__ out) {
    __shared__ double sred[256];
    int t = threadIdx.x;
    double s = 0;
    for (int k = t; k < 528;  k += 256) s += g_pb[k];
    for (int k = t; k < 1024; k += 256) s += g_pc[k];
    sred[t] = s;
    __syncthreads();
    for (int off = 128; off; off >>= 1) { if (t < off) sred[t] += sred[t + off]; __syncthreads(); }
    if (t == 0) out[0] = (float)(-(sred[0] / 67108864.0) * 100.0);
}

// ---------------- launch ----------------
extern "C" void kernel_launch(void* const* d_in, const int* in_sizes, int n_in,
                              void* d_out, int out_size) {
    const float* X; const float* LO;
    if (in_sizes[0] == N_PTS * DIMS) { X = (const float*)d_in[0]; LO = (const float*)d_in[1]; }
    else                             { X = (const float*)d_in[1]; LO = (const float*)d_in[0]; }

    cudaFuncSetAttribute(thresh_kernel, cudaFuncAttributeMaxDynamicSharedMemorySize, T_TOT);

    prep_kernel  <<<N_PTS / 8, 256>>>(X);
    thresh_kernel<<<128, 256, T_TOT>>>();
    filter_kernel<<<NPAIR, 256>>>();
    select_topk  <<<N_PTS / 8, 256>>>();
    bulk_kernel  <<<528, 256>>>(LO);
    corr_kernel  <<<N_PTS / 8, 256>>>(X, LO);
    final_kernel <<<1, 256>>>((float*)d_out);
}